// round 1
// baseline (speedup 1.0000x reference)
#include <cuda_runtime.h>
#include <cuda_bf16.h>
#include <cstdint>
#include <cstddef>

// ---------------- problem constants ----------------
#define NVOX   196608
#define CDIM   192
#define SETS   4096
#define SETSZ  48
#define NHEAD  8
#define HD     24
#define DFF    384

// ---------------- scratch (device globals; no allocation allowed) ----------
__device__ float g_qkin[(size_t)NVOX * CDIM];   // set-slot order: src+pos gathered
__device__ float g_feat[(size_t)NVOX * CDIM];   // set-slot order: src gathered
__device__ float g_qk  [(size_t)NVOX * 2 * CDIM]; // q (cols 0..191), k (192..383)
__device__ float g_v   [(size_t)NVOX * CDIM];
__device__ float g_ctx [(size_t)NVOX * CDIM];
__device__ float g_src2[(size_t)NVOX * CDIM];   // attn out-proj, set-slot order
__device__ float g_x   [(size_t)NVOX * CDIM];   // after LN1, voxel order
__device__ float g_h   [(size_t)NVOX * DFF];    // FFN hidden
__device__ float g_ffn [(size_t)NVOX * CDIM];   // FFN output

// ---------------- gather: qkin = src[v]+pos[v], feat = src[v] ---------------
__global__ void gather_kernel(const float* __restrict__ src,
                              const float* __restrict__ pos,
                              const int*   __restrict__ vidx)
{
    size_t i = (size_t)blockIdx.x * blockDim.x + threadIdx.x; // over NVOX*48 float4
    size_t total = (size_t)NVOX * (CDIM / 4);
    if (i >= total) return;
    int slot = (int)(i / (CDIM / 4));
    int c4   = (int)(i % (CDIM / 4));
    int v = vidx[slot];
    const float4* s4 = (const float4*)src;
    const float4* p4 = (const float4*)pos;
    float4 s = s4[(size_t)v * (CDIM / 4) + c4];
    float4 p = p4[(size_t)v * (CDIM / 4) + c4];
    ((float4*)g_feat)[i] = s;
    float4 q;
    q.x = s.x + p.x; q.y = s.y + p.y; q.z = s.z + p.z; q.w = s.w + p.w;
    ((float4*)g_qkin)[i] = q;
}

// ---------------- generic NT GEMM: C[m,n] = sum_k A[m,k]*B[n,k] + bias[n] ---
// A: MxK row-major, B: NxK row-major (weight layout of torch Linear), C: MxN.
// BM=BN=64, BK=16, 256 threads, 4x4 register tile. M,N,K multiples of 64/64/16.
#define BM 64
#define BN 64
#define BK 16

template <int RELU>
__global__ void __launch_bounds__(256)
gemm_nt(const float* __restrict__ A, const float* __restrict__ B,
        const float* __restrict__ bias, float* __restrict__ C,
        int M, int N, int K)
{
    __shared__ float As[BK][BM + 4];
    __shared__ float Bs[BK][BN + 4];

    int tid = threadIdx.x;
    int tx = tid & 15;        // 0..15 -> output col group
    int ty = tid >> 4;        // 0..15 -> output row group
    int row0 = blockIdx.x * BM;
    int col0 = blockIdx.y * BN;

    float acc[4][4];
    #pragma unroll
    for (int i = 0; i < 4; i++)
        #pragma unroll
        for (int j = 0; j < 4; j++) acc[i][j] = 0.f;

    int lr = tid >> 2;          // 0..63 : tile row to load
    int lk = (tid & 3) * 4;     // 0,4,8,12 : k offset (float4)

    for (int k0 = 0; k0 < K; k0 += BK) {
        float4 a = *(const float4*)&A[(size_t)(row0 + lr) * K + k0 + lk];
        As[lk + 0][lr] = a.x; As[lk + 1][lr] = a.y;
        As[lk + 2][lr] = a.z; As[lk + 3][lr] = a.w;
        float4 b = *(const float4*)&B[(size_t)(col0 + lr) * K + k0 + lk];
        Bs[lk + 0][lr] = b.x; Bs[lk + 1][lr] = b.y;
        Bs[lk + 2][lr] = b.z; Bs[lk + 3][lr] = b.w;
        __syncthreads();

        #pragma unroll
        for (int kk = 0; kk < BK; kk++) {
            float ra[4], rb[4];
            #pragma unroll
            for (int i = 0; i < 4; i++) ra[i] = As[kk][ty * 4 + i];
            #pragma unroll
            for (int j = 0; j < 4; j++) rb[j] = Bs[kk][tx * 4 + j];
            #pragma unroll
            for (int i = 0; i < 4; i++)
                #pragma unroll
                for (int j = 0; j < 4; j++)
                    acc[i][j] += ra[i] * rb[j];
        }
        __syncthreads();
    }

    int c = col0 + tx * 4;
    float4 bsv = *(const float4*)&bias[c];
    #pragma unroll
    for (int i = 0; i < 4; i++) {
        int r = row0 + ty * 4 + i;
        float4 o;
        o.x = acc[i][0] + bsv.x;
        o.y = acc[i][1] + bsv.y;
        o.z = acc[i][2] + bsv.z;
        o.w = acc[i][3] + bsv.w;
        if (RELU) {
            o.x = fmaxf(o.x, 0.f); o.y = fmaxf(o.y, 0.f);
            o.z = fmaxf(o.z, 0.f); o.w = fmaxf(o.w, 0.f);
        }
        *(float4*)&C[(size_t)r * N + c] = o;
    }
}

// ---------------- attention: one block per (set, head) ----------------------
__global__ void __launch_bounds__(128)
attn_kernel(const uint8_t* __restrict__ mask)
{
    int s = blockIdx.x;
    int h = blockIdx.y;
    int tid = threadIdx.x;

    __shared__ float qs[SETSZ][HD];
    __shared__ float ks[SETSZ][HD];
    __shared__ float vs[SETSZ][HD + 1];
    __shared__ float sc[SETSZ][SETSZ + 1];
    __shared__ float mflag[SETSZ];

    // load q,k,v slices for this (set, head)
    for (int e = tid; e < SETSZ * HD; e += 128) {
        int i = e / HD, d = e % HD;
        size_t rowqk = ((size_t)s * SETSZ + i) * (2 * CDIM) + h * HD + d;
        qs[i][d] = g_qk[rowqk];
        ks[i][d] = g_qk[rowqk + CDIM];
        vs[i][d] = g_v[((size_t)s * SETSZ + i) * CDIM + h * HD + d];
    }
    if (tid < SETSZ)
        mflag[tid] = (mask[(size_t)s * SETSZ + tid] != 0) ? -1e9f : 0.f;
    __syncthreads();

    // scores
    const float scale = 0.20412414523193154f; // 1/sqrt(24)
    for (int e = tid; e < SETSZ * SETSZ; e += 128) {
        int i = e / SETSZ, j = e % SETSZ;
        float acc = 0.f;
        #pragma unroll
        for (int d = 0; d < HD; d++) acc += qs[i][d] * ks[j][d];
        sc[i][j] = acc * scale + mflag[j];
    }
    __syncthreads();

    // row softmax (one thread per row)
    if (tid < SETSZ) {
        float m = -1e30f;
        #pragma unroll 4
        for (int j = 0; j < SETSZ; j++) m = fmaxf(m, sc[tid][j]);
        float sum = 0.f;
        #pragma unroll 4
        for (int j = 0; j < SETSZ; j++) {
            float e = __expf(sc[tid][j] - m);
            sc[tid][j] = e;
            sum += e;
        }
        float inv = 1.f / sum;
        #pragma unroll 4
        for (int j = 0; j < SETSZ; j++) sc[tid][j] *= inv;
    }
    __syncthreads();

    // ctx = attn @ v
    for (int e = tid; e < SETSZ * HD; e += 128) {
        int i = e / HD, d = e % HD;
        float acc = 0.f;
        #pragma unroll 4
        for (int j = 0; j < SETSZ; j++) acc += sc[i][j] * vs[j][d];
        g_ctx[((size_t)s * SETSZ + i) * CDIM + h * HD + d] = acc;
    }
}

// ---------------- scatter + residual + LN1 (warp per slot row) --------------
__global__ void __launch_bounds__(256)
scatter_ln1(const float* __restrict__ src, const int* __restrict__ vidx,
            const float* __restrict__ g, const float* __restrict__ b)
{
    int warp = (blockIdx.x * blockDim.x + threadIdx.x) >> 5;
    int lane = threadIdx.x & 31;
    if (warp >= NVOX) return;
    int v = vidx[warp];

    float vals[6];
    float s1 = 0.f, s2 = 0.f;
    #pragma unroll
    for (int t = 0; t < 6; t++) {
        int c = lane + t * 32;
        float val = src[(size_t)v * CDIM + c] + g_src2[(size_t)warp * CDIM + c];
        vals[t] = val;
        s1 += val; s2 += val * val;
    }
    #pragma unroll
    for (int o = 16; o > 0; o >>= 1) {
        s1 += __shfl_xor_sync(0xFFFFFFFFu, s1, o);
        s2 += __shfl_xor_sync(0xFFFFFFFFu, s2, o);
    }
    float mean = s1 * (1.f / CDIM);
    float var  = s2 * (1.f / CDIM) - mean * mean;
    float inv  = rsqrtf(var + 1e-5f);
    #pragma unroll
    for (int t = 0; t < 6; t++) {
        int c = lane + t * 32;
        g_x[(size_t)v * CDIM + c] = (vals[t] - mean) * inv * g[c] + b[c];
    }
}

// --------- fused: t = LN2(x + ffn); out = LN3(t + src) (warp per row) -------
__global__ void __launch_bounds__(256)
ln23_kernel(const float* __restrict__ src,
            const float* __restrict__ g2, const float* __restrict__ b2,
            const float* __restrict__ g3, const float* __restrict__ b3,
            float* __restrict__ out)
{
    int warp = (blockIdx.x * blockDim.x + threadIdx.x) >> 5;
    int lane = threadIdx.x & 31;
    if (warp >= NVOX) return;

    float vals[6];
    float s1 = 0.f, s2 = 0.f;
    #pragma unroll
    for (int t = 0; t < 6; t++) {
        int c = lane + t * 32;
        float val = g_x[(size_t)warp * CDIM + c] + g_ffn[(size_t)warp * CDIM + c];
        vals[t] = val;
        s1 += val; s2 += val * val;
    }
    #pragma unroll
    for (int o = 16; o > 0; o >>= 1) {
        s1 += __shfl_xor_sync(0xFFFFFFFFu, s1, o);
        s2 += __shfl_xor_sync(0xFFFFFFFFu, s2, o);
    }
    float mean = s1 * (1.f / CDIM);
    float var  = s2 * (1.f / CDIM) - mean * mean;
    float inv  = rsqrtf(var + 1e-5f);

    // second stage: t2 + identity(src), LN3
    float u[6];
    s1 = 0.f; s2 = 0.f;
    #pragma unroll
    for (int t = 0; t < 6; t++) {
        int c = lane + t * 32;
        float t2 = (vals[t] - mean) * inv * g2[c] + b2[c];
        float uu = t2 + src[(size_t)warp * CDIM + c];
        u[t] = uu;
        s1 += uu; s2 += uu * uu;
    }
    #pragma unroll
    for (int o = 16; o > 0; o >>= 1) {
        s1 += __shfl_xor_sync(0xFFFFFFFFu, s1, o);
        s2 += __shfl_xor_sync(0xFFFFFFFFu, s2, o);
    }
    float mean3 = s1 * (1.f / CDIM);
    float var3  = s2 * (1.f / CDIM) - mean3 * mean3;
    float inv3  = rsqrtf(var3 + 1e-5f);
    #pragma unroll
    for (int t = 0; t < 6; t++) {
        int c = lane + t * 32;
        out[(size_t)warp * CDIM + c] = (u[t] - mean3) * inv3 * g3[c] + b3[c];
    }
}

// ---------------- launch --------------------------------------------------
extern "C" void kernel_launch(void* const* d_in, const int* in_sizes, int n_in,
                              void* d_out, int out_size)
{
    const float* src   = (const float*)d_in[0];
    const float* pos   = (const float*)d_in[1];
    const float* w_qkv = (const float*)d_in[2];
    const float* b_qkv = (const float*)d_in[3];
    const float* w_out = (const float*)d_in[4];
    const float* b_out = (const float*)d_in[5];
    const float* w1    = (const float*)d_in[6];
    const float* b1    = (const float*)d_in[7];
    const float* w2    = (const float*)d_in[8];
    const float* b2    = (const float*)d_in[9];
    const float* ln1g  = (const float*)d_in[10];
    const float* ln1b  = (const float*)d_in[11];
    const float* ln2g  = (const float*)d_in[12];
    const float* ln2b  = (const float*)d_in[13];
    const float* ln3g  = (const float*)d_in[14];
    const float* ln3b  = (const float*)d_in[15];
    const int*   vidx  = (const int*)d_in[16];
    const uint8_t* msk = (const uint8_t*)d_in[17];
    float* out = (float*)d_out;

    float *p_qkin, *p_feat, *p_qk, *p_v, *p_ctx, *p_src2, *p_x, *p_h, *p_ffn;
    cudaGetSymbolAddress((void**)&p_qkin, g_qkin);
    cudaGetSymbolAddress((void**)&p_feat, g_feat);
    cudaGetSymbolAddress((void**)&p_qk,   g_qk);
    cudaGetSymbolAddress((void**)&p_v,    g_v);
    cudaGetSymbolAddress((void**)&p_ctx,  g_ctx);
    cudaGetSymbolAddress((void**)&p_src2, g_src2);
    cudaGetSymbolAddress((void**)&p_x,    g_x);
    cudaGetSymbolAddress((void**)&p_h,    g_h);
    cudaGetSymbolAddress((void**)&p_ffn,  g_ffn);

    // 1) gather into set-slot order
    {
        size_t total = (size_t)NVOX * (CDIM / 4);
        int thr = 256;
        int blocks = (int)((total + thr - 1) / thr);
        gather_kernel<<<blocks, thr>>>(src, pos, vidx);
    }

    const int MROWS = NVOX / BM;  // 3072

    // 2) q,k projection: (N x 384) = qkin @ [Wq;Wk]^T
    gemm_nt<0><<<dim3(MROWS, (2 * CDIM) / BN), 256>>>(p_qkin, w_qkv, b_qkv,
                                                      p_qk, NVOX, 2 * CDIM, CDIM);
    // 3) v projection: (N x 192) = feat @ Wv^T
    gemm_nt<0><<<dim3(MROWS, CDIM / BN), 256>>>(p_feat, w_qkv + (size_t)2 * CDIM * CDIM,
                                                b_qkv + 2 * CDIM, p_v, NVOX, CDIM, CDIM);
    // 4) attention per (set, head)
    attn_kernel<<<dim3(SETS, NHEAD), 128>>>(msk);

    // 5) output projection
    gemm_nt<0><<<dim3(MROWS, CDIM / BN), 256>>>(p_ctx, w_out, b_out,
                                                p_src2, NVOX, CDIM, CDIM);

    // 6) scatter back + residual + LN1 -> g_x (voxel order)
    {
        int warps_per_block = 8;
        int blocks = NVOX / warps_per_block;
        scatter_ln1<<<blocks, 256>>>(src, vidx, ln1g, ln1b);
    }

    // 7) FFN
    gemm_nt<1><<<dim3(MROWS, DFF / BN), 256>>>(p_x, w1, b1, p_h, NVOX, DFF, CDIM);
    gemm_nt<0><<<dim3(MROWS, CDIM / BN), 256>>>(p_h, w2, b2, p_ffn, NVOX, CDIM, DFF);

    // 8) LN2 + residual + LN3 -> out
    {
        int blocks = NVOX / 8;
        ln23_kernel<<<blocks, 256>>>(src, ln2g, ln2b, ln3g, ln3b, out);
    }
}

// round 2
// speedup vs baseline: 1.8798x; 1.8798x over previous
#include <cuda_runtime.h>
#include <cuda_bf16.h>
#include <cstdint>
#include <cstddef>

// ---------------- problem constants ----------------
#define NVOX   196608
#define CDIM   192
#define SETS   4096
#define SETSZ  48
#define NHEAD  8
#define HD     24
#define DFF    384

// ---------------- scratch (device globals; no allocation allowed) ----------
__device__ float g_qkin[(size_t)NVOX * CDIM];     // set-slot order: src+pos
__device__ float g_feat[(size_t)NVOX * CDIM];     // set-slot order: src
__device__ float g_qk  [(size_t)NVOX * 2 * CDIM]; // q cols 0..191, k 192..383
__device__ float g_v   [(size_t)NVOX * CDIM];
__device__ float g_ctx [(size_t)NVOX * CDIM];
__device__ float g_src2[(size_t)NVOX * CDIM];     // attn out-proj, set-slot order
__device__ float g_x   [(size_t)NVOX * CDIM];     // after LN1, voxel order
__device__ float g_h   [(size_t)NVOX * DFF];      // FFN hidden
__device__ float g_ffn [(size_t)NVOX * CDIM];     // FFN output

// ---------------- gather: qkin = src[v]+pos[v], feat = src[v] ---------------
__global__ void gather_kernel(const float* __restrict__ src,
                              const float* __restrict__ pos,
                              const int*   __restrict__ vidx)
{
    size_t i = (size_t)blockIdx.x * blockDim.x + threadIdx.x;
    size_t total = (size_t)NVOX * (CDIM / 4);
    if (i >= total) return;
    int slot = (int)(i / (CDIM / 4));
    int c4   = (int)(i % (CDIM / 4));
    int v = vidx[slot];
    const float4* s4 = (const float4*)src;
    const float4* p4 = (const float4*)pos;
    float4 s = s4[(size_t)v * (CDIM / 4) + c4];
    float4 p = p4[(size_t)v * (CDIM / 4) + c4];
    ((float4*)g_feat)[i] = s;
    float4 q;
    q.x = s.x + p.x; q.y = s.y + p.y; q.z = s.z + p.z; q.w = s.w + p.w;
    ((float4*)g_qkin)[i] = q;
}

// ---------------- bf16x3 tensor-core GEMM ----------------------------------
// C[m,n] = sum_k A[m,k]*B[n,k] + bias[n]   (A: MxK rm, B: NxK rm, C: MxN rm)
// fp32 operands split hi/lo bf16; 3 mma per tile (hh + hl + lh) ~ fp32 accuracy.
// BM=128, BN=64, BK=32, 256 threads (8 warps as 2x4), warp tile 64x16.

#define ASTR 20   // smem row stride in u32 pairs (16 data + 4 pad, conflict-free)

__device__ __forceinline__ void split_pack(float x, float y, uint32_t& h, uint32_t& l)
{
    __nv_bfloat162 h2 = __floats2bfloat162_rn(x, y);
    h = *reinterpret_cast<const uint32_t*>(&h2);
    float rx = x - __bfloat162float(h2.x);
    float ry = y - __bfloat162float(h2.y);
    __nv_bfloat162 l2 = __floats2bfloat162_rn(rx, ry);
    l = *reinterpret_cast<const uint32_t*>(&l2);
}

__device__ __forceinline__ void mma_bf16(float c[4],
    uint32_t a0, uint32_t a1, uint32_t a2, uint32_t a3,
    uint32_t b0, uint32_t b1)
{
    asm volatile(
        "mma.sync.aligned.m16n8k16.row.col.f32.bf16.bf16.f32 "
        "{%0,%1,%2,%3}, {%4,%5,%6,%7}, {%8,%9}, {%0,%1,%2,%3};\n"
        : "+f"(c[0]), "+f"(c[1]), "+f"(c[2]), "+f"(c[3])
        : "r"(a0), "r"(a1), "r"(a2), "r"(a3), "r"(b0), "r"(b1));
}

template <int RELU>
__global__ void __launch_bounds__(256)
gemm_bf16x3(const float* __restrict__ A, const float* __restrict__ B,
            const float* __restrict__ bias, float* __restrict__ C,
            int M, int N, int K)
{
    __shared__ uint32_t Ah[128 * ASTR];
    __shared__ uint32_t Al[128 * ASTR];
    __shared__ uint32_t Bh[64 * ASTR];
    __shared__ uint32_t Bl[64 * ASTR];

    const int tid  = threadIdx.x;
    const int lane = tid & 31;
    const int warp = tid >> 5;
    const int wr   = warp >> 2;   // 0..1
    const int wc   = warp & 3;    // 0..3
    const int row0 = blockIdx.x * 128;
    const int col0 = blockIdx.y * 64;

    float acc[4][2][4];
    #pragma unroll
    for (int m = 0; m < 4; m++)
        #pragma unroll
        for (int n = 0; n < 2; n++)
            #pragma unroll
            for (int i = 0; i < 4; i++) acc[m][n][i] = 0.f;

    const int ar = tid >> 3;   // 0..31 : tile row for loads
    const int ac = tid & 7;    // 0..7  : float4 column

    for (int k0 = 0; k0 < K; k0 += 32) {
        // ---- load + split A tile (128x32) ----
        #pragma unroll
        for (int r = 0; r < 4; r++) {
            int row = ar + r * 32;
            float4 v = *(const float4*)&A[(size_t)(row0 + row) * K + k0 + ac * 4];
            uint32_t h0, l0, h1, l1;
            split_pack(v.x, v.y, h0, l0);
            split_pack(v.z, v.w, h1, l1);
            Ah[row * ASTR + ac * 2]     = h0;
            Ah[row * ASTR + ac * 2 + 1] = h1;
            Al[row * ASTR + ac * 2]     = l0;
            Al[row * ASTR + ac * 2 + 1] = l1;
        }
        // ---- load + split B tile (64x32) ----
        #pragma unroll
        for (int r = 0; r < 2; r++) {
            int row = ar + r * 32;
            float4 v = *(const float4*)&B[(size_t)(col0 + row) * K + k0 + ac * 4];
            uint32_t h0, l0, h1, l1;
            split_pack(v.x, v.y, h0, l0);
            split_pack(v.z, v.w, h1, l1);
            Bh[row * ASTR + ac * 2]     = h0;
            Bh[row * ASTR + ac * 2 + 1] = h1;
            Bl[row * ASTR + ac * 2]     = l0;
            Bl[row * ASTR + ac * 2 + 1] = l1;
        }
        __syncthreads();

        #pragma unroll
        for (int k16 = 0; k16 < 2; k16++) {
            const int kp = k16 * 8 + (lane & 3);
            uint32_t bh[2][2], bl[2][2];
            #pragma unroll
            for (int nt = 0; nt < 2; nt++) {
                int n = wc * 16 + nt * 8 + (lane >> 2);
                bh[nt][0] = Bh[n * ASTR + kp];
                bh[nt][1] = Bh[n * ASTR + kp + 4];
                bl[nt][0] = Bl[n * ASTR + kp];
                bl[nt][1] = Bl[n * ASTR + kp + 4];
            }
            #pragma unroll
            for (int mt = 0; mt < 4; mt++) {
                int rl = wr * 64 + mt * 16 + (lane >> 2);
                int rh = rl + 8;
                uint32_t ah0 = Ah[rl * ASTR + kp];
                uint32_t ah1 = Ah[rh * ASTR + kp];
                uint32_t ah2 = Ah[rl * ASTR + kp + 4];
                uint32_t ah3 = Ah[rh * ASTR + kp + 4];
                uint32_t al0 = Al[rl * ASTR + kp];
                uint32_t al1 = Al[rh * ASTR + kp];
                uint32_t al2 = Al[rl * ASTR + kp + 4];
                uint32_t al3 = Al[rh * ASTR + kp + 4];
                #pragma unroll
                for (int nt = 0; nt < 2; nt++) {
                    mma_bf16(acc[mt][nt], ah0, ah1, ah2, ah3, bh[nt][0], bh[nt][1]);
                    mma_bf16(acc[mt][nt], ah0, ah1, ah2, ah3, bl[nt][0], bl[nt][1]);
                    mma_bf16(acc[mt][nt], al0, al1, al2, al3, bh[nt][0], bh[nt][1]);
                }
            }
        }
        __syncthreads();
    }

    // ---- epilogue: bias (+relu), fp32 store ----
    #pragma unroll
    for (int mt = 0; mt < 4; mt++) {
        int r0 = row0 + wr * 64 + mt * 16 + (lane >> 2);
        #pragma unroll
        for (int nt = 0; nt < 2; nt++) {
            int c = col0 + wc * 16 + nt * 8 + 2 * (lane & 3);
            float bx = bias[c], by = bias[c + 1];
            float2 o0, o1;
            o0.x = acc[mt][nt][0] + bx; o0.y = acc[mt][nt][1] + by;
            o1.x = acc[mt][nt][2] + bx; o1.y = acc[mt][nt][3] + by;
            if (RELU) {
                o0.x = fmaxf(o0.x, 0.f); o0.y = fmaxf(o0.y, 0.f);
                o1.x = fmaxf(o1.x, 0.f); o1.y = fmaxf(o1.y, 0.f);
            }
            *(float2*)&C[(size_t)r0 * N + c]       = o0;
            *(float2*)&C[(size_t)(r0 + 8) * N + c] = o1;
        }
    }
}

// ---------------- attention: one block (64 thr) per (set, head) -------------
// Thread i (<48) holds q-row, score row, and output row in registers.
__global__ void __launch_bounds__(64)
attn_kernel(const uint8_t* __restrict__ mask)
{
    int s = blockIdx.x;
    int h = blockIdx.y;
    int tid = threadIdx.x;

    __shared__ float qs[SETSZ][28];
    __shared__ float ks[SETSZ][28];
    __shared__ float vs[SETSZ][28];
    __shared__ float mf[SETSZ];

    for (int e = tid; e < SETSZ * HD; e += 64) {
        int i = e / HD, d = e % HD;
        size_t rowqk = ((size_t)s * SETSZ + i) * (2 * CDIM) + h * HD + d;
        qs[i][d] = g_qk[rowqk];
        ks[i][d] = g_qk[rowqk + CDIM];
        vs[i][d] = g_v[((size_t)s * SETSZ + i) * CDIM + h * HD + d];
    }
    if (tid < SETSZ)
        mf[tid] = (mask[(size_t)s * SETSZ + tid] != 0) ? -1e9f : 0.f;
    __syncthreads();

    if (tid < SETSZ) {
        const float scale = 0.20412414523193154f; // 1/sqrt(24)
        float4 q[6];
        #pragma unroll
        for (int t = 0; t < 6; t++) q[t] = *(const float4*)&qs[tid][t * 4];

        float sc[SETSZ];
        #pragma unroll
        for (int j = 0; j < SETSZ; j++) {
            float a = 0.f;
            #pragma unroll
            for (int t = 0; t < 6; t++) {
                float4 k4 = *(const float4*)&ks[j][t * 4];
                a += q[t].x * k4.x + q[t].y * k4.y + q[t].z * k4.z + q[t].w * k4.w;
            }
            sc[j] = a * scale + mf[j];
        }
        float m = -1e30f;
        #pragma unroll
        for (int j = 0; j < SETSZ; j++) m = fmaxf(m, sc[j]);
        float sum = 0.f;
        #pragma unroll
        for (int j = 0; j < SETSZ; j++) { float e = __expf(sc[j] - m); sc[j] = e; sum += e; }
        float inv = 1.f / sum;

        float4 o[6];
        #pragma unroll
        for (int t = 0; t < 6; t++) { o[t].x = 0.f; o[t].y = 0.f; o[t].z = 0.f; o[t].w = 0.f; }
        #pragma unroll
        for (int j = 0; j < SETSZ; j++) {
            float p = sc[j] * inv;
            #pragma unroll
            for (int t = 0; t < 6; t++) {
                float4 v4 = *(const float4*)&vs[j][t * 4];
                o[t].x += p * v4.x; o[t].y += p * v4.y;
                o[t].z += p * v4.z; o[t].w += p * v4.w;
            }
        }
        // stage result in own qs row (no one else reads it)
        #pragma unroll
        for (int t = 0; t < 6; t++) *(float4*)&qs[tid][t * 4] = o[t];
    }
    __syncthreads();

    for (int e = tid; e < SETSZ * HD; e += 64) {
        int i = e / HD, d = e % HD;
        g_ctx[((size_t)s * SETSZ + i) * CDIM + h * HD + d] = qs[i][d];
    }
}

// ---------------- scatter + residual + LN1 (warp per slot row) --------------
__global__ void __launch_bounds__(256)
scatter_ln1(const float* __restrict__ src, const int* __restrict__ vidx,
            const float* __restrict__ g, const float* __restrict__ b)
{
    int warp = (blockIdx.x * blockDim.x + threadIdx.x) >> 5;
    int lane = threadIdx.x & 31;
    if (warp >= NVOX) return;
    int v = vidx[warp];

    float vals[6];
    float s1 = 0.f, s2 = 0.f;
    #pragma unroll
    for (int t = 0; t < 6; t++) {
        int c = lane + t * 32;
        float val = src[(size_t)v * CDIM + c] + g_src2[(size_t)warp * CDIM + c];
        vals[t] = val;
        s1 += val; s2 += val * val;
    }
    #pragma unroll
    for (int o = 16; o > 0; o >>= 1) {
        s1 += __shfl_xor_sync(0xFFFFFFFFu, s1, o);
        s2 += __shfl_xor_sync(0xFFFFFFFFu, s2, o);
    }
    float mean = s1 * (1.f / CDIM);
    float var  = s2 * (1.f / CDIM) - mean * mean;
    float inv  = rsqrtf(var + 1e-5f);
    #pragma unroll
    for (int t = 0; t < 6; t++) {
        int c = lane + t * 32;
        g_x[(size_t)v * CDIM + c] = (vals[t] - mean) * inv * g[c] + b[c];
    }
}

// --------- fused: t = LN2(x + ffn); out = LN3(t + src) (warp per row) -------
__global__ void __launch_bounds__(256)
ln23_kernel(const float* __restrict__ src,
            const float* __restrict__ g2, const float* __restrict__ b2,
            const float* __restrict__ g3, const float* __restrict__ b3,
            float* __restrict__ out)
{
    int warp = (blockIdx.x * blockDim.x + threadIdx.x) >> 5;
    int lane = threadIdx.x & 31;
    if (warp >= NVOX) return;

    float vals[6];
    float s1 = 0.f, s2 = 0.f;
    #pragma unroll
    for (int t = 0; t < 6; t++) {
        int c = lane + t * 32;
        float val = g_x[(size_t)warp * CDIM + c] + g_ffn[(size_t)warp * CDIM + c];
        vals[t] = val;
        s1 += val; s2 += val * val;
    }
    #pragma unroll
    for (int o = 16; o > 0; o >>= 1) {
        s1 += __shfl_xor_sync(0xFFFFFFFFu, s1, o);
        s2 += __shfl_xor_sync(0xFFFFFFFFu, s2, o);
    }
    float mean = s1 * (1.f / CDIM);
    float var  = s2 * (1.f / CDIM) - mean * mean;
    float inv  = rsqrtf(var + 1e-5f);

    float u[6];
    s1 = 0.f; s2 = 0.f;
    #pragma unroll
    for (int t = 0; t < 6; t++) {
        int c = lane + t * 32;
        float t2 = (vals[t] - mean) * inv * g2[c] + b2[c];
        float uu = t2 + src[(size_t)warp * CDIM + c];
        u[t] = uu;
        s1 += uu; s2 += uu * uu;
    }
    #pragma unroll
    for (int o = 16; o > 0; o >>= 1) {
        s1 += __shfl_xor_sync(0xFFFFFFFFu, s1, o);
        s2 += __shfl_xor_sync(0xFFFFFFFFu, s2, o);
    }
    float mean3 = s1 * (1.f / CDIM);
    float var3  = s2 * (1.f / CDIM) - mean3 * mean3;
    float inv3  = rsqrtf(var3 + 1e-5f);
    #pragma unroll
    for (int t = 0; t < 6; t++) {
        int c = lane + t * 32;
        out[(size_t)warp * CDIM + c] = (u[t] - mean3) * inv3 * g3[c] + b3[c];
    }
}

// ---------------- launch --------------------------------------------------
extern "C" void kernel_launch(void* const* d_in, const int* in_sizes, int n_in,
                              void* d_out, int out_size)
{
    const float* src   = (const float*)d_in[0];
    const float* pos   = (const float*)d_in[1];
    const float* w_qkv = (const float*)d_in[2];
    const float* b_qkv = (const float*)d_in[3];
    const float* w_out = (const float*)d_in[4];
    const float* b_out = (const float*)d_in[5];
    const float* w1    = (const float*)d_in[6];
    const float* b1    = (const float*)d_in[7];
    const float* w2    = (const float*)d_in[8];
    const float* b2    = (const float*)d_in[9];
    const float* ln1g  = (const float*)d_in[10];
    const float* ln1b  = (const float*)d_in[11];
    const float* ln2g  = (const float*)d_in[12];
    const float* ln2b  = (const float*)d_in[13];
    const float* ln3g  = (const float*)d_in[14];
    const float* ln3b  = (const float*)d_in[15];
    const int*   vidx  = (const int*)d_in[16];
    const uint8_t* msk = (const uint8_t*)d_in[17];
    float* out = (float*)d_out;

    float *p_qkin, *p_feat, *p_qk, *p_v, *p_ctx, *p_src2, *p_x, *p_h, *p_ffn;
    cudaGetSymbolAddress((void**)&p_qkin, g_qkin);
    cudaGetSymbolAddress((void**)&p_feat, g_feat);
    cudaGetSymbolAddress((void**)&p_qk,   g_qk);
    cudaGetSymbolAddress((void**)&p_v,    g_v);
    cudaGetSymbolAddress((void**)&p_ctx,  g_ctx);
    cudaGetSymbolAddress((void**)&p_src2, g_src2);
    cudaGetSymbolAddress((void**)&p_x,    g_x);
    cudaGetSymbolAddress((void**)&p_h,    g_h);
    cudaGetSymbolAddress((void**)&p_ffn,  g_ffn);

    // 1) gather into set-slot order
    {
        size_t total = (size_t)NVOX * (CDIM / 4);
        int thr = 256;
        int blocks = (int)((total + thr - 1) / thr);
        gather_kernel<<<blocks, thr>>>(src, pos, vidx);
    }

    const int MB = NVOX / 128;  // 1536

    // 2) q,k projection: (N x 384)
    gemm_bf16x3<0><<<dim3(MB, (2 * CDIM) / 64), 256>>>(p_qkin, w_qkv, b_qkv,
                                                       p_qk, NVOX, 2 * CDIM, CDIM);
    // 3) v projection: (N x 192)
    gemm_bf16x3<0><<<dim3(MB, CDIM / 64), 256>>>(p_feat, w_qkv + (size_t)2 * CDIM * CDIM,
                                                 b_qkv + 2 * CDIM, p_v, NVOX, CDIM, CDIM);
    // 4) attention per (set, head)
    attn_kernel<<<dim3(SETS, NHEAD), 64>>>(msk);

    // 5) output projection
    gemm_bf16x3<0><<<dim3(MB, CDIM / 64), 256>>>(p_ctx, w_out, b_out,
                                                 p_src2, NVOX, CDIM, CDIM);

    // 6) scatter back + residual + LN1 -> g_x (voxel order)
    scatter_ln1<<<NVOX / 8, 256>>>(src, vidx, ln1g, ln1b);

    // 7) FFN
    gemm_bf16x3<1><<<dim3(MB, DFF / 64), 256>>>(p_x, w1, b1, p_h, NVOX, DFF, CDIM);
    gemm_bf16x3<0><<<dim3(MB, CDIM / 64), 256>>>(p_h, w2, b2, p_ffn, NVOX, CDIM, DFF);

    // 8) LN2 + residual + LN3 -> out
    ln23_kernel<<<NVOX / 8, 256>>>(src, ln2g, ln2b, ln3g, ln3b, out);
}